// round 3
// baseline (speedup 1.0000x reference)
#include <cuda_runtime.h>
#include <cuda_bf16.h>
#include <math.h>

#define NB 4
#define H  512
#define W  360
#define D  512

// Filtered sinogram, layout [w][h][b] so backprojection reads float4 per (w,h).
__device__ float g_F[(size_t)W * H * NB];

// ---------------------------------------------------------------------------
// Kernel 1: circular ramp filtering.
//   out[b][w][h] = sum_k hG[k] * radon[b][(h + 257 + k) & 511][w]
// Grid: 360 blocks of 128 threads. Block = (batch, group of 4 angles).
// Each thread computes 4 consecutive h outputs for each of the 4 angles,
// using an 8-float register sliding window per angle (aligned LDS.128).
// ---------------------------------------------------------------------------
__global__ __launch_bounds__(128) void filter_kernel(
    const float* __restrict__ radon,  // [NB][H][W]
    const float* __restrict__ hG)     // [H]
{
    __shared__ float sh_x[4][1032];   // per-angle rotated/duplicated column
    __shared__ float sh_h[512];

    const int tid   = threadIdx.x;
    const int batch = blockIdx.x / (W / 4);
    const int w0    = (blockIdx.x % (W / 4)) * 4;

    // Load filter taps.
    #pragma unroll
    for (int i = tid; i < 512; i += 128) sh_h[i] = hG[i];

    // Load rotated columns: sh_x[a][i] = radon[batch][(i+257)&511][w0+a]
    // One float4 per i covers the 4 consecutive angles (16B aligned since
    // w0%4==0 and W%4==0).
    const float* rb = radon + (size_t)batch * H * W;
    for (int i = tid; i < 1028; i += 128) {
        const int hsrc = (i + 257) & 511;
        const float4 v = *reinterpret_cast<const float4*>(rb + (size_t)hsrc * W + w0);
        sh_x[0][i] = v.x; sh_x[1][i] = v.y; sh_x[2][i] = v.z; sh_x[3][i] = v.w;
    }
    __syncthreads();

    const int h0 = tid * 4;           // this thread's 4 output rows

    float acc[4][4];
    #pragma unroll
    for (int a = 0; a < 4; a++)
        #pragma unroll
        for (int j = 0; j < 4; j++) acc[a][j] = 0.0f;

    float wn[4][8];                   // sliding windows, one per angle
    #pragma unroll
    for (int a = 0; a < 4; a++) {
        const float4 v0 = *reinterpret_cast<const float4*>(&sh_x[a][h0]);
        const float4 v1 = *reinterpret_cast<const float4*>(&sh_x[a][h0 + 4]);
        wn[a][0] = v0.x; wn[a][1] = v0.y; wn[a][2] = v0.z; wn[a][3] = v0.w;
        wn[a][4] = v1.x; wn[a][5] = v1.y; wn[a][6] = v1.z; wn[a][7] = v1.w;
    }

    #pragma unroll 2
    for (int k = 0; k < 512; k += 4) {
        const float4 hv = *reinterpret_cast<const float4*>(&sh_h[k]);
        const float hvv[4] = {hv.x, hv.y, hv.z, hv.w};
        #pragma unroll
        for (int a = 0; a < 4; a++) {
            #pragma unroll
            for (int s = 0; s < 4; s++) {
                #pragma unroll
                for (int j = 0; j < 4; j++)
                    acc[a][j] = fmaf(hvv[s], wn[a][s + j], acc[a][j]);
            }
            // slide window by 4 taps
            const float4 nv = *reinterpret_cast<const float4*>(&sh_x[a][h0 + k + 8]);
            wn[a][0] = wn[a][4]; wn[a][1] = wn[a][5];
            wn[a][2] = wn[a][6]; wn[a][3] = wn[a][7];
            wn[a][4] = nv.x; wn[a][5] = nv.y; wn[a][6] = nv.z; wn[a][7] = nv.w;
        }
    }

    // Store to [w][h][b]
    #pragma unroll
    for (int a = 0; a < 4; a++)
        #pragma unroll
        for (int j = 0; j < 4; j++)
            g_F[((size_t)(w0 + a) * H + (h0 + j)) * NB + batch] = acc[a][j];
}

// ---------------------------------------------------------------------------
// Kernel 2: backprojection. One thread per output pixel, 4 batch accumulators.
//   py = (t_y[w,i,j] + 1) * 0.5 * (H-1); linear interp along h with zero
//   weights outside [0,H); BOTH y0 and y1 clipped independently (matches
//   jnp.clip in the reference — matters when y0 == -1, where w1 = fy != 0
//   and the reference reads col[0], not col[1]).
// t_y is a one-shot 377MB stream -> __ldcs (evict-streaming) so it doesn't
// evict the hot per-angle F working set (~8KB/angle) from L1.
// ---------------------------------------------------------------------------
__global__ __launch_bounds__(256) void backproj_kernel(
    const float* __restrict__ t_y,    // [W][D][D]
    float* __restrict__ out)          // [NB][D][D]
{
    const int j = blockIdx.x * 32 + threadIdx.x;
    const int i = blockIdx.y * 8  + threadIdx.y;

    const float4* __restrict__ F4 = reinterpret_cast<const float4*>(g_F);
    const float* tp = t_y + (size_t)i * D + j;

    float a0 = 0.0f, a1 = 0.0f, a2 = 0.0f, a3 = 0.0f;
    int fbase = 0;

    #pragma unroll 4
    for (int w = 0; w < W; ++w) {
        const float tyv = __ldcs(tp);
        tp += D * D;

        const float py  = (tyv + 1.0f) * 0.5f * 511.0f;
        const float y0f = floorf(py);
        const float fy  = py - y0f;
        const int   y0  = (int)y0f;

        const float w0 = (y0 >= 0 && y0 < H)      ? (1.0f - fy) : 0.0f;
        const float w1 = (y0 >= -1 && y0 < H - 1) ? fy          : 0.0f;

        const int c0 = min(max(y0, 0), H - 1);
        const int c1 = min(max(y0 + 1, 0), H - 1);

        const float4 f0 = __ldg(&F4[fbase + c0]);
        const float4 f1 = __ldg(&F4[fbase + c1]);

        a0 = fmaf(f0.x, w0, a0); a0 = fmaf(f1.x, w1, a0);
        a1 = fmaf(f0.y, w0, a1); a1 = fmaf(f1.y, w1, a1);
        a2 = fmaf(f0.z, w0, a2); a2 = fmaf(f1.z, w1, a2);
        a3 = fmaf(f0.w, w0, a3); a3 = fmaf(f1.w, w1, a3);

        fbase += H;
    }

    const float s = (float)(M_PI / (2.0 * (double)W));
    const size_t p = (size_t)i * D + j;
    out[p]                 = a0 * s;
    out[p + (size_t)D*D]   = a1 * s;
    out[p + 2*(size_t)D*D] = a2 * s;
    out[p + 3*(size_t)D*D] = a3 * s;
}

// ---------------------------------------------------------------------------
extern "C" void kernel_launch(void* const* d_in, const int* in_sizes, int n_in,
                              void* d_out, int out_size)
{
    const float* radon = nullptr;
    const float* hg    = nullptr;
    const float* ty    = nullptr;
    for (int k = 0; k < n_in; k++) {
        const int sz = in_sizes[k];
        if (sz == NB * H * W)            radon = (const float*)d_in[k];
        else if (sz == H)                hg    = (const float*)d_in[k];
        else if (sz == W * D * D)        ty    = (const float*)d_in[k];
    }

    filter_kernel<<<360, 128>>>(radon, hg);

    dim3 grid(D / 32, D / 8);
    dim3 block(32, 8);
    backproj_kernel<<<grid, block>>>(ty, (float*)d_out);
}